// round 16
// baseline (speedup 1.0000x reference)
#include <cuda_runtime.h>

#define TWO_PI_F 6.283185307179586f
#define NROT 8
#define C_DIM 128
#define KS 5
#define PATCH 25
#define TPB 416                     // 13 warps = one per active tap
#define NWARP 13
#define CIN_CHUNK 32
#define NACT 13
#define OGRP 4
#define ACT_MASK 0x477DC4u          // bit p set iff X^2+Y^2 <= 1 on 5x5 grid
#define OUT_CI_STRIDE (NROT * C_DIM * 200)   // 204800

__device__ __constant__ int APLIST[NACT] = {2,6,7,8,10,11,12,13,14,16,17,18,22};

__device__ __forceinline__ unsigned smem_u32(const void* p) {
    return (unsigned)__cvta_generic_to_shared(p);
}

// stage word address: rotated layout, CF for STS(lanes=ci) and LDS(lanes=chunk)
__device__ __forceinline__ int stg_addr(int r, int ci) {
    return r * 32 + ((ci + (r >> 2)) & 31);
}

__global__ __launch_bounds__(TPB)
void gk_r16_kernel(const float* __restrict__ in_H,
                   const float* __restrict__ out_H,
                   const float* __restrict__ weight,
                   float* __restrict__ out)
{
    __shared__ float  slab[NROT * 800];        // 25.6 KB [g][ci32][q25]
    __shared__ float  stage[200 * 32];         // 25.6 KB rotated [r][ci]
    __shared__ float  c8[OGRP * 64];           // [oo][g][i] Gk-mix coefficients
    __shared__ float4 ctab[OGRP * NACT];       // bilinear corner weights
    __shared__ int4   qtab[OGRP * NACT];       // bilinear corner indices

    const int co      = blockIdx.x;
    const int ci_base = blockIdx.y * CIN_CHUNK;
    const int o_base  = blockIdx.z * OGRP;
    const int tid     = threadIdx.x;
    const int w       = tid >> 5;      // warp = pa (phase A), row-group (store)
    const int lane    = tid & 31;      // lane = ci (phase A), chunk (store)

    // ---- fill slab with cp.async ----
    {
        const float4* __restrict__ w4 = (const float4*)weight;
#pragma unroll
        for (int k = 0; k < 4; ++k) {
            int f = tid + k * TPB;                   // float4 index 0..1599
            if (f < 1600) {
                int g = f / 200;
                int r = f - g * 200;
                size_t gb4 = ((size_t)((g * C_DIM + co) * C_DIM + ci_base) * PATCH) >> 2;
                unsigned dst = smem_u32(&slab[g * 800 + r * 4]);
                asm volatile("cp.async.cg.shared.global [%0], [%1], 16;\n"
                             :: "r"(dst), "l"(w4 + gb4 + r) : "memory");
            }
        }
        asm volatile("cp.async.commit_group;\n" ::: "memory");
    }

    // ---- zero stage once: inactive (r,ci) slots stay 0 for all oo ----
    for (int z = tid; z < 200 * 32; z += TPB) stage[z] = 0.0f;

    // ---- Gk-mix coefficient matrix c8[oo][g][i] ----
    if (tid < OGRP * 64) {
        const int oo = tid >> 6, g = (tid >> 3) & 7, i = tid & 7;
        const float outH  = out_H[o_base + oo];
        const float theta = in_H[i] - outH;
        const float tmod  = theta - floorf(theta * (1.0f / TWO_PI_F)) * TWO_PI_F;
        const float pos   = tmod * ((float)NROT / TWO_PI_F);
        int g0 = ((int)floorf(pos)) % NROT;
        if (g0 >= NROT) g0 -= NROT;
        const int g1 = (g0 + 1) & (NROT - 1);
        const float frac = pos - floorf(pos);
        float c = 0.0f;
        if (g == g0) c += 1.0f - frac;
        if (g == g1) c += frac;
        c8[tid] = c;
    }

    // ---- per-(oo,pa) bilinear tables ----
    if (tid < OGRP * NACT) {
        const int oo = tid / NACT, pa = tid - oo * NACT;
        const int p  = APLIST[pa];
        const int px = p % KS, py = p / KS;
        const float X = -1.0f + 0.5f * (float)px;
        const float Y = -1.0f + 0.5f * (float)py;
        const float outH = out_H[o_base + oo];
        const float cc = cosf(-outH), ss = sinf(-outH);
        const float gx = cc * X - ss * Y;
        const float gy = ss * X + cc * Y;
        const float sx = fmaf(gx, 2.0f, 2.0f);
        const float sy = fmaf(gy, 2.0f, 2.0f);
        const float fxf = floorf(sx), fyf = floorf(sy);
        const float fx = sx - fxf, fy = sy - fyf;
        int x0 = min(max((int)fxf, 0), KS - 1);
        int y0 = min(max((int)fyf, 0), KS - 1);
        const int x1 = min(x0 + 1, KS - 1);
        const int y1 = min(y0 + 1, KS - 1);
        ctab[tid] = make_float4((1.0f - fy) * (1.0f - fx), (1.0f - fy) * fx,
                                fy * (1.0f - fx),          fy * fx);
        qtab[tid] = make_int4(y0 * KS + x0, y0 * KS + x1,
                              y1 * KS + x0, y1 * KS + x1);
    }

    const int p = APLIST[w];       // this warp's tap (w < 13 always)

    asm volatile("cp.async.wait_group 0;\n" ::: "memory");
    __syncthreads();

    for (int oo = 0; oo < OGRP; ++oo) {
        // ---- phase A: per-thread (pa=w, ci=lane): 8-g bilinear + register Gk mix ----
        {
            const int4   q  = qtab[oo * NACT + w];   // broadcast
            const float4 cw = ctab[oo * NACT + w];   // broadcast
            const float* sb = slab + lane * PATCH;   // lanes stride 25: CF

            float a0 = 0.f, a1 = 0.f, a2 = 0.f, a3 = 0.f;
            float a4 = 0.f, a5 = 0.f, a6 = 0.f, a7 = 0.f;
#pragma unroll
            for (int g = 0; g < NROT; ++g) {
                const float* sg = sb + g * 800;
                float v;
                v = cw.x * sg[q.x];
                v = fmaf(cw.y, sg[q.y], v);
                v = fmaf(cw.z, sg[q.z], v);
                v = fmaf(cw.w, sg[q.w], v);
                const float4 ca = *(const float4*)&c8[oo * 64 + g * 8];     // broadcast
                const float4 cb = *(const float4*)&c8[oo * 64 + g * 8 + 4]; // broadcast
                a0 = fmaf(ca.x, v, a0); a1 = fmaf(ca.y, v, a1);
                a2 = fmaf(ca.z, v, a2); a3 = fmaf(ca.w, v, a3);
                a4 = fmaf(cb.x, v, a4); a5 = fmaf(cb.y, v, a5);
                a6 = fmaf(cb.z, v, a6); a7 = fmaf(cb.w, v, a7);
            }
            // rotated stage: fixed r, lanes=ci -> banks (ci+rb)&31 distinct: CF
            stage[stg_addr(0 * PATCH + p, lane)] = a0;
            stage[stg_addr(1 * PATCH + p, lane)] = a1;
            stage[stg_addr(2 * PATCH + p, lane)] = a2;
            stage[stg_addr(3 * PATCH + p, lane)] = a3;
            stage[stg_addr(4 * PATCH + p, lane)] = a4;
            stage[stg_addr(5 * PATCH + p, lane)] = a5;
            stage[stg_addr(6 * PATCH + p, lane)] = a6;
            stage[stg_addr(7 * PATCH + p, lane)] = a7;
        }
        __syncthreads();

        // ---- store: vectorized STG.128; lanes 0..24 = float4 chunks ----
        if (lane < 25) {
#pragma unroll
            for (int rowk = 0; rowk < 3; ++rowk) {
                const int ci = w + rowk * NWARP;
                if (ci < CIN_CHUNK) {
                    float* orow = out + (size_t)(ci_base + ci) * OUT_CI_STRIDE
                                      + (size_t)((o_base + oo) * C_DIM + co) * 200;
#pragma unroll
                    for (int half = 0; half < 2; ++half) {
                        const int kk = lane + half * 25;     // chunk 0..49
                        const int rot = (ci + kk) & 31;      // hoisted rotation
                        const int base = 4 * kk * 32 + rot;
                        float4 v;
                        v.x = stage[base];                   // lanes: banks (ci+kk)&31 CF
                        v.y = stage[base + 32];
                        v.z = stage[base + 64];
                        v.w = stage[base + 96];
                        *(float4*)(orow + 4 * kk) = v;       // STG.128, coalesced
                    }
                }
            }
        }
        __syncthreads();   // stage reused next oo
    }
}

extern "C" void kernel_launch(void* const* d_in, const int* in_sizes, int n_in,
                              void* d_out, int out_size)
{
    const float* in_H   = (const float*)d_in[0];
    const float* out_H  = (const float*)d_in[1];
    const float* weight = (const float*)d_in[2];
    float* out = (float*)d_out;

    dim3 grid(C_DIM, C_DIM / CIN_CHUNK, NROT / OGRP);   // 1024 blocks
    gk_r16_kernel<<<grid, TPB>>>(in_H, out_H, weight, out);
}

// round 17
// speedup vs baseline: 1.4722x; 1.4722x over previous
#include <cuda_runtime.h>

#define TWO_PI_F 6.283185307179586f
#define NROT 8
#define C_DIM 128
#define KS 5
#define PATCH 25
#define TPB 416                     // 13 warps = one per active tap
#define NWARP 13
#define CIN_CHUNK 32
#define NACT 13
#define OGRP 4
#define ACT_MASK 0x477DC4u          // bit p set iff X^2+Y^2 <= 1 on 5x5 grid
#define OUT_CI_STRIDE (NROT * C_DIM * 200)   // 204800
#define SPAD 33                     // stage [r200][ci32] row stride (CF both ways)

__device__ __constant__ int APLIST[NACT] = {2,6,7,8,10,11,12,13,14,16,17,18,22};

__device__ __forceinline__ unsigned smem_u32(const void* p) {
    return (unsigned)__cvta_generic_to_shared(p);
}

__global__ __launch_bounds__(TPB, 4)
void gk_r17_kernel(const float* __restrict__ in_H,
                   const float* __restrict__ out_H,
                   const float* __restrict__ weight,
                   float* __restrict__ out)
{
    __shared__ float  slab[NROT * 800];        // 25.6 KB [g][ci32][q25]
    __shared__ float  stage[200 * SPAD];       // 26.4 KB [r][ci], pad 33
    __shared__ float  c8[OGRP * 64];           // [oo][g][i] Gk-mix coefficients
    __shared__ float4 ctab[OGRP * NACT];       // bilinear corner weights
    __shared__ int4   qtab[OGRP * NACT];       // bilinear corner indices

    const int co      = blockIdx.x;
    const int ci_base = blockIdx.y * CIN_CHUNK;
    const int o_base  = blockIdx.z * OGRP;
    const int tid     = threadIdx.x;
    const int w       = tid >> 5;      // warp = pa (phase A), row-group (store)
    const int lane    = tid & 31;      // lane = ci (phase A), r-chunk (store)

    // ---- fill slab with cp.async ----
    {
        const float4* __restrict__ w4 = (const float4*)weight;
#pragma unroll
        for (int k = 0; k < 4; ++k) {
            int f = tid + k * TPB;                   // float4 index 0..1599
            if (f < 1600) {
                int g = f / 200;
                int r = f - g * 200;
                size_t gb4 = ((size_t)((g * C_DIM + co) * C_DIM + ci_base) * PATCH) >> 2;
                unsigned dst = smem_u32(&slab[g * 800 + r * 4]);
                asm volatile("cp.async.cg.shared.global [%0], [%1], 16;\n"
                             :: "r"(dst), "l"(w4 + gb4 + r) : "memory");
            }
        }
        asm volatile("cp.async.commit_group;\n" ::: "memory");
    }

    // ---- zero stage once: inactive rows stay 0 for all oo ----
    for (int z = tid; z < 200 * SPAD; z += TPB) stage[z] = 0.0f;

    // ---- Gk-mix coefficient matrix c8[oo][g][i] ----
    if (tid < OGRP * 64) {
        const int oo = tid >> 6, g = (tid >> 3) & 7, i = tid & 7;
        const float outH  = out_H[o_base + oo];
        const float theta = in_H[i] - outH;
        const float tmod  = theta - floorf(theta * (1.0f / TWO_PI_F)) * TWO_PI_F;
        const float pos   = tmod * ((float)NROT / TWO_PI_F);
        int g0 = ((int)floorf(pos)) % NROT;
        if (g0 >= NROT) g0 -= NROT;
        const int g1 = (g0 + 1) & (NROT - 1);
        const float frac = pos - floorf(pos);
        float c = 0.0f;
        if (g == g0) c += 1.0f - frac;
        if (g == g1) c += frac;
        c8[tid] = c;
    }

    // ---- per-(oo,pa) bilinear tables ----
    if (tid < OGRP * NACT) {
        const int oo = tid / NACT, pa = tid - oo * NACT;
        const int p  = APLIST[pa];
        const int px = p % KS, py = p / KS;
        const float X = -1.0f + 0.5f * (float)px;
        const float Y = -1.0f + 0.5f * (float)py;
        const float outH = out_H[o_base + oo];
        const float cc = cosf(-outH), ss = sinf(-outH);
        const float gx = cc * X - ss * Y;
        const float gy = ss * X + cc * Y;
        const float sx = fmaf(gx, 2.0f, 2.0f);
        const float sy = fmaf(gy, 2.0f, 2.0f);
        const float fxf = floorf(sx), fyf = floorf(sy);
        const float fx = sx - fxf, fy = sy - fyf;
        int x0 = min(max((int)fxf, 0), KS - 1);
        int y0 = min(max((int)fyf, 0), KS - 1);
        const int x1 = min(x0 + 1, KS - 1);
        const int y1 = min(y0 + 1, KS - 1);
        ctab[tid] = make_float4((1.0f - fy) * (1.0f - fx), (1.0f - fy) * fx,
                                fy * (1.0f - fx),          fy * fx);
        qtab[tid] = make_int4(y0 * KS + x0, y0 * KS + x1,
                              y1 * KS + x0, y1 * KS + x1);
    }

    const int p = APLIST[w];       // this warp's tap (w < 13 always)

    asm volatile("cp.async.wait_group 0;\n" ::: "memory");
    __syncthreads();

    for (int oo = 0; oo < OGRP; ++oo) {
        // ---- phase A: per-thread (pa=w, ci=lane): 8-g bilinear + register Gk mix ----
        {
            const int4   q  = qtab[oo * NACT + w];   // broadcast
            const float4 cw = ctab[oo * NACT + w];   // broadcast
            const float* sb = slab + lane * PATCH;   // lanes stride 25: CF

            float a0 = 0.f, a1 = 0.f, a2 = 0.f, a3 = 0.f;
            float a4 = 0.f, a5 = 0.f, a6 = 0.f, a7 = 0.f;
#pragma unroll
            for (int g = 0; g < NROT; ++g) {
                const float* sg = sb + g * 800;
                float v;
                v = cw.x * sg[q.x];
                v = fmaf(cw.y, sg[q.y], v);
                v = fmaf(cw.z, sg[q.z], v);
                v = fmaf(cw.w, sg[q.w], v);
                const float4 ca = *(const float4*)&c8[oo * 64 + g * 8];     // broadcast
                const float4 cb = *(const float4*)&c8[oo * 64 + g * 8 + 4]; // broadcast
                a0 = fmaf(ca.x, v, a0); a1 = fmaf(ca.y, v, a1);
                a2 = fmaf(ca.z, v, a2); a3 = fmaf(ca.w, v, a3);
                a4 = fmaf(cb.x, v, a4); a5 = fmaf(cb.y, v, a5);
                a6 = fmaf(cb.z, v, a6); a7 = fmaf(cb.w, v, a7);
            }
            // stage[(i*25+p)][ci]: lanes consecutive -> CF
            stage[(0 * PATCH + p) * SPAD + lane] = a0;
            stage[(1 * PATCH + p) * SPAD + lane] = a1;
            stage[(2 * PATCH + p) * SPAD + lane] = a2;
            stage[(3 * PATCH + p) * SPAD + lane] = a3;
            stage[(4 * PATCH + p) * SPAD + lane] = a4;
            stage[(5 * PATCH + p) * SPAD + lane] = a5;
            stage[(6 * PATCH + p) * SPAD + lane] = a6;
            stage[(7 * PATCH + p) * SPAD + lane] = a7;
        }
        __syncthreads();

        // ---- store: row ci = w, w+13, w+26; lanes span r (CF LDS, coalesced STG) ----
        {
#pragma unroll
            for (int rowk = 0; rowk < 3; ++rowk) {
                const int ci = w + rowk * NWARP;
                if (ci < CIN_CHUNK) {
                    const float* srow = stage + ci;        // addr = r*33 + ci
                    float* orow = out + (size_t)(ci_base + ci) * OUT_CI_STRIDE
                                      + (size_t)((o_base + oo) * C_DIM + co) * 200;
#pragma unroll
                    for (int rc = 0; rc < 7; ++rc) {
                        const int r = rc * 32 + lane;
                        if (r < 200)
                            orow[r] = srow[r * SPAD];      // stride 33: CF; STG coalesced
                    }
                }
            }
        }
        __syncthreads();   // stage reused next oo
    }
}

extern "C" void kernel_launch(void* const* d_in, const int* in_sizes, int n_in,
                              void* d_out, int out_size)
{
    const float* in_H   = (const float*)d_in[0];
    const float* out_H  = (const float*)d_in[1];
    const float* weight = (const float*)d_in[2];
    float* out = (float*)d_out;

    dim3 grid(C_DIM, C_DIM / CIN_CHUNK, NROT / OGRP);   // 1024 blocks
    gk_r17_kernel<<<grid, TPB>>>(in_H, out_H, weight, out);
}